// round 16
// baseline (speedup 1.0000x reference)
#include <cuda_runtime.h>
#include <math.h>

#define NQ       12
#define NPATCH   196
#define BATCH    4
#define NROWS    784        // BATCH * NPATCH
#define FEATDIM  2352       // NPATCH * NQ
#define FULLMASK 0xffffffffu

typedef unsigned long long u64;

// ---------------- device scratch (no allocations allowed) ----------------
__device__ float g_feats[NROWS * NQ];
__device__ float g_qkv[3 * NROWS * NQ];
__device__ float g_attn_out[NROWS * NQ];
__device__ float g_gcoef[3][80];      // per s: 40 gates x (0.5*cos2t, 0.5*sin2t)

// ---------------- packed f32x2 helpers (Blackwell) ----------------
__device__ __forceinline__ u64 pk2(float lo, float hi) {
    u64 r;
    asm("mov.b64 %0, {%1, %2};" : "=l"(r) : "r"(__float_as_uint(lo)), "r"(__float_as_uint(hi)));
    return r;
}
__device__ __forceinline__ void upk2(float& lo, float& hi, u64 v) {
    unsigned a, b;
    asm("mov.b64 {%0, %1}, %2;" : "=r"(a), "=r"(b) : "l"(v));
    lo = __uint_as_float(a); hi = __uint_as_float(b);
}
__device__ __forceinline__ u64 add2_(u64 a, u64 b) {
    u64 r; asm("add.rn.f32x2 %0, %1, %2;" : "=l"(r) : "l"(a), "l"(b)); return r;
}
__device__ __forceinline__ u64 mul2_(u64 a, u64 b) {
    u64 r; asm("mul.rn.f32x2 %0, %1, %2;" : "=l"(r) : "l"(a), "l"(b)); return r;
}
__device__ __forceinline__ u64 fma2_(u64 a, u64 b, u64 c) {
    u64 r; asm("fma.rn.f32x2 %0, %1, %2, %3;" : "=l"(r) : "l"(a), "l"(b), "l"(c)); return r;
}
__device__ __forceinline__ u64 shfl2(u64 v, int msk) {
    unsigned a, b;
    asm("mov.b64 {%0, %1}, %2;" : "=r"(a), "=r"(b) : "l"(v));
    a = __shfl_xor_sync(FULLMASK, a, msk);
    b = __shfl_xor_sync(FULLMASK, b, msk);
    u64 r;
    asm("mov.b64 %0, {%1, %2};" : "=l"(r) : "r"(a), "r"(b));
    return r;
}

// ---------------- Kernel A: channel-mean + patchify + projection (+ coef fold) ----------------
__global__ void proj_kernel(const float* __restrict__ x,
                            const float* __restrict__ Wp,
                            const float* __restrict__ bp,
                            const float* __restrict__ qp,
                            const float* __restrict__ kp,
                            const float* __restrict__ vp) {
    int blk = blockIdx.x;                 // 0..783 = b*196 + p
    int b = blk / NPATCH, p = blk % NPATCH;
    int py = p / 14, px = p % 14;
    int j = threadIdx.x;                  // 0..255 patch element
    int r = j >> 4, c = j & 15;
    int h = py * 16 + r, w = px * 16 + c;
    long base = (long)b * 3 * 224 * 224 + (long)h * 224 + w;
    float v = (x[base] + x[base + 224 * 224] + x[base + 2 * 224 * 224]) * (1.0f / 3.0f);

    float acc[NQ];
#pragma unroll
    for (int k = 0; k < NQ; k++) acc[k] = v * Wp[k * 256 + j];

#pragma unroll
    for (int k = 0; k < NQ; k++) {
#pragma unroll
        for (int off = 16; off; off >>= 1)
            acc[k] += __shfl_down_sync(FULLMASK, acc[k], off);
    }
    __shared__ float sred[8][NQ];
    int warp = j >> 5, lane = j & 31;
    if (lane == 0) {
#pragma unroll
        for (int k = 0; k < NQ; k++) sred[warp][k] = acc[k];
    }
    __syncthreads();
    if (j < NQ) {
        float s = 0.f;
#pragma unroll
        for (int w8 = 0; w8 < 8; w8++) s += sred[w8][j];
        g_feats[blk * NQ + j] = s + bp[j];
    }

    // folded coefficient prep (block 0 only, threads 128..247)
    if (blk == 0 && j >= 128 && j < 248) {
        int t = j - 128;
        int s = t / 40, gg = t % 40;
        const float* pp = (s == 0) ? qp : (s == 1) ? kp : vp;
        int l = gg / 20, g = gg % 20;
        float th = pp[l * 32 + g];        // pidx == gate index within layer
        float s2, c2; sincosf(2.0f * th, &s2, &c2);
        g_gcoef[s][2 * gg + 0] = 0.5f * c2;
        g_gcoef[s][2 * gg + 1] = 0.5f * s2;
    }
}

// ---------------- quantum gate primitives (packed warp-register state) ----------------
// Scalar amp index i = (lane << 7) | (k << 1) | h.
//   packed bit h      <-> qubit 11
//   A-reg bits 0..5   <-> qubits {8, 7, 4, 3, 2, 1}
//   lane bits 0..4    <-> qubits {10, 9, 6, 5, 0}
// ch = 0.5*cos2t, sh = 0.5*sin2t everywhere. neg1 = packed (-1,-1).

// w1-bit in lane (LBIT), w2-bit in A-regs (MLA); packed bit untouched
template<int LBIT, int MLA>
__device__ __forceinline__ void gM(u64* A, u64 ch2, u64 sgnsh2, u64 half2, u64 neg1) {
    const int msk = 1 << LBIT;
#pragma unroll
    for (int k = 0; k < 64; k++) {
        if ((k & MLA) == 0) {
            u64 s  = add2_(A[k], A[k | MLA]);
            u64 d  = fma2_(A[k | MLA], neg1, A[k]);
            u64 od = shfl2(d, msk);
            u64 h  = fma2_(sgnsh2, od, mul2_(ch2, d));
            u64 sv = mul2_(half2, s);
            A[k]       = add2_(sv, h);
            A[k | MLA] = fma2_(h, neg1, sv);
        }
    }
}

// w1-bit in lane (LBIT), w2-bit = packed bit
template<int LBIT>
__device__ __forceinline__ void gMp(u64* A, float ch, float sgnsh) {
    const int msk = 1 << LBIT;
#pragma unroll
    for (int k = 0; k < 64; k++) {
        float x0, x1; upk2(x0, x1, A[k]);
        float s = x0 + x1, d = x0 - x1;
        float od = __shfl_xor_sync(FULLMASK, d, msk);
        float h = fmaf(ch, d, sgnsh * od);
        float sv = 0.5f * s;
        A[k] = pk2(sv + h, sv - h);
    }
}

// w2-bit in lane (LBIT), w1-bit in A-regs (MHA); branch-free
template<int LBIT, int MHA>
__device__ __forceinline__ void gMlo(u64* A, u64 ch2, u64 sh2, u64 nsh2, u64 half2, u64 neg1) {
    const int msk = 1 << LBIT;
#pragma unroll
    for (int k = 0; k < 64; k++) {
        if ((k & MHA) == 0) {
            u64 x0 = A[k], x1 = A[k | MHA];
            u64 y0 = shfl2(x0, msk);
            u64 y1 = shfl2(x1, msk);
            u64 dx = fma2_(y0, neg1, x0);
            u64 dq = fma2_(y1, neg1, x1);
            u64 uh = mul2_(half2, add2_(x0, y0));
            u64 ph = mul2_(half2, add2_(x1, y1));
            A[k]       = fma2_(nsh2, dq, fma2_(ch2, dx, uh));
            A[k | MHA] = fma2_(ch2, dq, fma2_(sh2, dx, ph));
        }
    }
}

// both bits in A-regs (MHA = w1, MLA = w2)
template<int MHA, int MLA>
__device__ __forceinline__ void gR(u64* A, u64 ch2, u64 sh2, u64 nsh2, u64 half2, u64 neg1) {
#pragma unroll
    for (int k = 0; k < 64; k++) {
        if ((k & (MHA | MLA)) == 0) {
            u64 e00 = A[k], e01 = A[k | MLA], e10 = A[k | MHA], e11 = A[k | MHA | MLA];
            u64 u = add2_(e00, e01), v = fma2_(e01, neg1, e00);
            u64 p = add2_(e10, e11), q = fma2_(e11, neg1, e10);
            u64 hv = fma2_(nsh2, q, mul2_(ch2, v));
            u64 hq = fma2_(ch2, q, mul2_(sh2, v));
            u64 uh = mul2_(half2, u), ph = mul2_(half2, p);
            A[k]             = add2_(uh, hv);
            A[k | MLA]       = fma2_(hv, neg1, uh);
            A[k | MHA]       = add2_(ph, hq);
            A[k | MHA | MLA] = fma2_(hq, neg1, ph);
        }
    }
}

// w1-bit in A-regs (MHA), w2-bit = packed bit
template<int MHA>
__device__ __forceinline__ void gRp(u64* A, float ch, float sh) {
#pragma unroll
    for (int k = 0; k < 64; k++) {
        if ((k & MHA) == 0) {
            float e00, e01, e10, e11;
            upk2(e00, e01, A[k]);
            upk2(e10, e11, A[k | MHA]);
            float u = e00 + e01, v = e00 - e01;
            float p = e10 + e11, q = e10 - e11;
            float hv = fmaf(ch, v, -sh * q);
            float hq = fmaf(sh, v,  ch * q);
            float uh = 0.5f * u, ph = 0.5f * p;
            A[k]       = pk2(uh + hv, uh - hv);
            A[k | MHA] = pk2(ph + hq, ph - hq);
        }
    }
}

// ---------------- Kernel B: warp-per-state quantum evolution ----------------
// 64-thread blocks, launch_bounds(64,5): reg cap ~204 -> 10 warps/SM (2.5/SMSP)
__global__ void __launch_bounds__(64, 5) quantum_kernel() {
    int warp = threadIdx.x >> 5, lane = threadIdx.x & 31;
    int unit = blockIdx.x * 2 + warp;       // 0..2351
    int row = unit % NROWS;
    int s = unit / NROWS;                   // 0..2

    __shared__ float shco[2][80];
    {
        const float* gc = g_gcoef[s];
        for (int i = lane; i < 80; i += 32) shco[warp][i] = gc[i];
        __syncwarp();
    }
    const float* co = shco[warp];

    const u64 half2 = pk2(0.5f, 0.5f);
    const u64 neg1  = pk2(-1.0f, -1.0f);

    // angle encoding: lane q<12 computes cos/sin(x_q/2), broadcast via shfl
    float ang = (lane < NQ) ? 0.5f * g_feats[row * NQ + lane] : 0.0f;
    float cv, sv; sincosf(ang, &sv, &cv);

    // phi over lane bits: lane bit b -> qubit {10,9,6,5,0}
    float phi = 1.0f;
    {
        float cb, sb;
        cb = __shfl_sync(FULLMASK, cv, 10); sb = __shfl_sync(FULLMASK, sv, 10);
        phi *= (lane & 1)  ? sb : cb;
        cb = __shfl_sync(FULLMASK, cv, 9);  sb = __shfl_sync(FULLMASK, sv, 9);
        phi *= (lane & 2)  ? sb : cb;
        cb = __shfl_sync(FULLMASK, cv, 6);  sb = __shfl_sync(FULLMASK, sv, 6);
        phi *= (lane & 4)  ? sb : cb;
        cb = __shfl_sync(FULLMASK, cv, 5);  sb = __shfl_sync(FULLMASK, sv, 5);
        phi *= (lane & 8)  ? sb : cb;
        cb = __shfl_sync(FULLMASK, cv, 0);  sb = __shfl_sync(FULLMASK, sv, 0);
        phi *= (lane & 16) ? sb : cb;
    }

    // product-state init: packed bit -> qubit 11; A-bits 0..5 -> {8,7,4,3,2,1}
    u64 A[64];
    {
        float c11 = __shfl_sync(FULLMASK, cv, 11);
        float s11 = __shfl_sync(FULLMASK, sv, 11);
        A[0] = pk2(phi * c11, phi * s11);
        const int rq6[6] = {8, 7, 4, 3, 2, 1};
#pragma unroll
        for (int m = 0; m < 6; m++) {
            float cm = __shfl_sync(FULLMASK, cv, rq6[m]);
            float sm = __shfl_sync(FULLMASK, sv, rq6[m]);
            u64 cm2 = pk2(cm, cm), sm2 = pk2(sm, sm);
            int len = 1 << m;
#pragma unroll
            for (int i = 0; i < 64; i++) {
                if (i < len) {
                    A[i + len] = mul2_(A[i], sm2);
                    A[i] = mul2_(A[i], cm2);
                }
            }
        }
    }

    // 2 layers x 20 gates
#pragma unroll 1
    for (int l = 0; l < 2; l++) {
        const float* c = co + l * 40;
        float ch, sh; u64 ch2, sh2, nsh2;
#define LDC(g) ch = c[2*(g)]; sh = c[2*(g)+1]; ch2 = pk2(ch, ch); sh2 = pk2(sh, sh); nsh2 = pk2(-sh, -sh);
        LDC(0);  gM<4, 32>(A, ch2, (lane & 16) ? sh2 : nsh2, half2, neg1);  // (q0,q1)
        LDC(1);  gR<16, 8>(A, ch2, sh2, nsh2, half2, neg1);                 // (q2,q3)
        LDC(2);  gMlo<3, 4>(A, ch2, sh2, nsh2, half2, neg1);                // (q4,q5)
        LDC(3);  gM<2, 2>(A, ch2, (lane & 4) ? sh2 : nsh2, half2, neg1);    // (q6,q7)
        LDC(4);  gMlo<1, 1>(A, ch2, sh2, nsh2, half2, neg1);                // (q8,q9)
        LDC(5);  gMp<0>(A, ch, (lane & 1) ? sh : -sh);                      // (q10,q11)
        LDC(6);  gM<4, 16>(A, ch2, (lane & 16) ? sh2 : nsh2, half2, neg1);  // (q0,q2)
        LDC(7);  gR<32, 8>(A, ch2, sh2, nsh2, half2, neg1);                 // (q1,q3)
        LDC(8);  gMlo<2, 4>(A, ch2, sh2, nsh2, half2, neg1);                // (q4,q6)
        LDC(9);  gM<3, 2>(A, ch2, (lane & 8) ? sh2 : nsh2, half2, neg1);    // (q5,q7)
        LDC(10); gMlo<0, 1>(A, ch2, sh2, nsh2, half2, neg1);                // (q8,q10)
        LDC(11); gMp<1>(A, ch, (lane & 2) ? sh : -sh);                      // (q9,q11)
        LDC(12); gM<4, 4>(A, ch2, (lane & 16) ? sh2 : nsh2, half2, neg1);   // (q0,q4)
        LDC(13); gMlo<3, 32>(A, ch2, sh2, nsh2, half2, neg1);               // (q1,q5)
        LDC(14); gMlo<2, 16>(A, ch2, sh2, nsh2, half2, neg1);               // (q2,q6)
        LDC(15); gR<8, 2>(A, ch2, sh2, nsh2, half2, neg1);                  // (q3,q7)
        LDC(16); gM<4, 1>(A, ch2, (lane & 16) ? sh2 : nsh2, half2, neg1);   // (q0,q8)
        LDC(17); gMlo<1, 32>(A, ch2, sh2, nsh2, half2, neg1);               // (q1,q9)
        LDC(18); gMlo<0, 16>(A, ch2, sh2, nsh2, half2, neg1);               // (q2,q10)
        LDC(19); gRp<8>(A, ch, sh);                                         // (q3,q11)
#undef LDC
    }

    // expvals: squares; packed bit fold gives <Z_11>; then fold A-bits
    float D11 = 0.0f;
    float bb[64];
#pragma unroll
    for (int k = 0; k < 64; k++) {
        float x0, x1; upk2(x0, x1, A[k]);
        float s0 = x0 * x0, s1 = x1 * x1;
        D11 += s0 - s1;
        bb[k] = s0 + s1;
    }
    float D[6];
#pragma unroll
    for (int m = 0; m < 6; m++) {
        int half = 64 >> (m + 1);
        float dsum = 0.0f;
#pragma unroll
        for (int i = 0; i < 32; i++) {
            if (i < half) {
                float lo = bb[2 * i], hi = bb[2 * i + 1];
                dsum += lo - hi;
                bb[i] = lo + hi;
            }
        }
        D[m] = dsum;
    }
    float S = bb[0];                         // per-lane total prob

    // reduce D over lanes
#pragma unroll
    for (int b = 0; b < 5; b++)
        D11 += __shfl_xor_sync(FULLMASK, D11, 1 << b);
#pragma unroll
    for (int m = 0; m < 6; m++) {
#pragma unroll
        for (int b = 0; b < 5; b++)
            D[m] += __shfl_xor_sync(FULLMASK, D[m], 1 << b);
    }

    // lane-bit qubits: signed reductions of S
    float L[5];
#pragma unroll
    for (int b = 0; b < 5; b++) {
        float o = __shfl_xor_sync(FULLMASK, S, 1 << b);
        L[b] = (lane & (1 << b)) ? (o - S) : (S - o);
        S += o;
    }
#pragma unroll
    for (int b = 0; b < 5; b++) {
#pragma unroll
        for (int b2 = b + 1; b2 < 5; b2++)
            L[b] += __shfl_xor_sync(FULLMASK, L[b], 1 << b2);
    }

    if (lane == 0) {
        float* dst = g_qkv + ((long)s * NROWS + row) * NQ;
        dst[11] = D11;
        dst[8] = D[0]; dst[7] = D[1]; dst[4] = D[2];
        dst[3] = D[3]; dst[2] = D[4]; dst[1] = D[5];
        dst[10] = L[0]; dst[9] = L[1]; dst[6] = L[2]; dst[5] = L[3]; dst[0] = L[4];
    }
}

// ---------------- Kernel C: attention, warp per query row ----------------
__global__ void attn_kernel() {
    int gw = blockIdx.x * 4 + (threadIdx.x >> 5);    // 0..783
    int lane = threadIdx.x & 31;
    int b = gw / NPATCH, q = gw % NPATCH;
    const float scale = 0.28867513459481287f;        // 1/sqrt(12)

    const float* Qr = g_qkv + ((long)0 * NROWS + b * NPATCH + q) * NQ;
    const float* Kb = g_qkv + ((long)1 * NROWS + b * NPATCH) * NQ;
    const float* Vb = g_qkv + ((long)2 * NROWS + b * NPATCH) * NQ;

    float4 q0 = *(const float4*)(Qr);
    float4 q1 = *(const float4*)(Qr + 4);
    float4 q2 = *(const float4*)(Qr + 8);

    float sc[7];
    float m = -1e30f;
#pragma unroll
    for (int i = 0; i < 7; i++) {
        int k = lane + 32 * i;
        float v = -1e30f;
        if (k < NPATCH) {
            const float* Kr = Kb + k * NQ;
            float4 k0 = *(const float4*)Kr;
            float4 k1 = *(const float4*)(Kr + 4);
            float4 k2 = *(const float4*)(Kr + 8);
            v = q0.x * k0.x + q0.y * k0.y + q0.z * k0.z + q0.w * k0.w
              + q1.x * k1.x + q1.y * k1.y + q1.z * k1.z + q1.w * k1.w
              + q2.x * k2.x + q2.y * k2.y + q2.z * k2.z + q2.w * k2.w;
            v *= scale;
        }
        sc[i] = v;
        m = fmaxf(m, v);
    }
#pragma unroll
    for (int off = 16; off; off >>= 1)
        m = fmaxf(m, __shfl_xor_sync(FULLMASK, m, off));

    float den = 0.f;
    float o[NQ];
#pragma unroll
    for (int d = 0; d < NQ; d++) o[d] = 0.f;
#pragma unroll
    for (int i = 0; i < 7; i++) {
        int k = lane + 32 * i;
        if (k < NPATCH) {
            float e = __expf(sc[i] - m);
            den += e;
            const float* Vr = Vb + k * NQ;
            float4 v0 = *(const float4*)Vr;
            float4 v1 = *(const float4*)(Vr + 4);
            float4 v2 = *(const float4*)(Vr + 8);
            o[0] += e * v0.x; o[1] += e * v0.y; o[2]  += e * v0.z; o[3]  += e * v0.w;
            o[4] += e * v1.x; o[5] += e * v1.y; o[6]  += e * v1.z; o[7]  += e * v1.w;
            o[8] += e * v2.x; o[9] += e * v2.y; o[10] += e * v2.z; o[11] += e * v2.w;
        }
    }
#pragma unroll
    for (int off = 16; off; off >>= 1) {
        den += __shfl_xor_sync(FULLMASK, den, off);
#pragma unroll
        for (int d = 0; d < NQ; d++)
            o[d] += __shfl_xor_sync(FULLMASK, o[d], off);
    }
    if (lane == 0) {
        float inv = 1.0f / den;
        float* dst = g_attn_out + ((long)b * NPATCH + q) * NQ;
#pragma unroll
        for (int d = 0; d < NQ; d++) dst[d] = o[d] * inv;
    }
}

// ---------------- Kernel D: classifier (float4, proven 1000x256) ----------------
__global__ void cls_kernel(const float* __restrict__ Wc,
                           const float* __restrict__ bc,
                           float* __restrict__ out) {
    int o = blockIdx.x;                   // 0..999
    int t = threadIdx.x;                  // 256
    const float4* W4 = (const float4*)(Wc + (long)o * FEATDIM);
    const float4* A4 = (const float4*)g_attn_out;   // [4][588] float4
    float a0 = 0.f, a1 = 0.f, a2 = 0.f, a3 = 0.f;
    const int NF4 = FEATDIM / 4;          // 588
    for (int j = t; j < NF4; j += 256) {
        float4 w = W4[j];
        float4 x0 = A4[j];
        float4 x1 = A4[NF4 + j];
        float4 x2 = A4[2 * NF4 + j];
        float4 x3 = A4[3 * NF4 + j];
        a0 += w.x * x0.x + w.y * x0.y + w.z * x0.z + w.w * x0.w;
        a1 += w.x * x1.x + w.y * x1.y + w.z * x1.z + w.w * x1.w;
        a2 += w.x * x2.x + w.y * x2.y + w.z * x2.z + w.w * x2.w;
        a3 += w.x * x3.x + w.y * x3.y + w.z * x3.z + w.w * x3.w;
    }
#pragma unroll
    for (int off = 16; off; off >>= 1) {
        a0 += __shfl_down_sync(FULLMASK, a0, off);
        a1 += __shfl_down_sync(FULLMASK, a1, off);
        a2 += __shfl_down_sync(FULLMASK, a2, off);
        a3 += __shfl_down_sync(FULLMASK, a3, off);
    }
    __shared__ float sred[8][4];
    int warp = t >> 5, lane = t & 31;
    if (lane == 0) { sred[warp][0] = a0; sred[warp][1] = a1; sred[warp][2] = a2; sred[warp][3] = a3; }
    __syncthreads();
    if (t == 0) {
        float bias = bc[o];
        float r0 = 0.f, r1 = 0.f, r2 = 0.f, r3 = 0.f;
#pragma unroll
        for (int w8 = 0; w8 < 8; w8++) {
            r0 += sred[w8][0]; r1 += sred[w8][1]; r2 += sred[w8][2]; r3 += sred[w8][3];
        }
        out[0 * 1000 + o] = r0 + bias;
        out[1 * 1000 + o] = r1 + bias;
        out[2 * 1000 + o] = r2 + bias;
        out[3 * 1000 + o] = r3 + bias;
    }
}

// ---------------- launcher ----------------
extern "C" void kernel_launch(void* const* d_in, const int* in_sizes, int n_in,
                              void* d_out, int out_size) {
    const float* x  = (const float*)d_in[0];
    const float* Wp = (const float*)d_in[1];
    const float* bp = (const float*)d_in[2];
    const float* qp = (const float*)d_in[3];
    const float* kp = (const float*)d_in[4];
    const float* vp = (const float*)d_in[5];
    const float* Wc = (const float*)d_in[6];
    const float* bc = (const float*)d_in[7];
    float* out = (float*)d_out;

    proj_kernel<<<NROWS, 256>>>(x, Wp, bp, qp, kp, vp);
    quantum_kernel<<<1176, 64>>>();
    attn_kernel<<<196, 128>>>();
    cls_kernel<<<1000, 256>>>(Wc, bc, out);
}

// round 17
// speedup vs baseline: 1.8216x; 1.8216x over previous
#include <cuda_runtime.h>
#include <math.h>

#define NQ       12
#define NPATCH   196
#define BATCH    4
#define NROWS    784        // BATCH * NPATCH
#define FEATDIM  2352       // NPATCH * NQ
#define FULLMASK 0xffffffffu

typedef unsigned long long u64;

// ---------------- device scratch (no allocations allowed) ----------------
__device__ float g_feats[NROWS * NQ];
__device__ float g_qkv[3 * NROWS * NQ];
__device__ float g_attn_out[NROWS * NQ];
__device__ float g_gcoef[3][80];      // per s: 40 gates x (0.5*cos2t, 0.5*sin2t)

// ---------------- packed f32x2 helpers (Blackwell) ----------------
__device__ __forceinline__ u64 pk2(float lo, float hi) {
    u64 r;
    asm("mov.b64 %0, {%1, %2};" : "=l"(r) : "r"(__float_as_uint(lo)), "r"(__float_as_uint(hi)));
    return r;
}
__device__ __forceinline__ void upk2(float& lo, float& hi, u64 v) {
    unsigned a, b;
    asm("mov.b64 {%0, %1}, %2;" : "=r"(a), "=r"(b) : "l"(v));
    lo = __uint_as_float(a); hi = __uint_as_float(b);
}
__device__ __forceinline__ u64 add2_(u64 a, u64 b) {
    u64 r; asm("add.rn.f32x2 %0, %1, %2;" : "=l"(r) : "l"(a), "l"(b)); return r;
}
__device__ __forceinline__ u64 mul2_(u64 a, u64 b) {
    u64 r; asm("mul.rn.f32x2 %0, %1, %2;" : "=l"(r) : "l"(a), "l"(b)); return r;
}
__device__ __forceinline__ u64 fma2_(u64 a, u64 b, u64 c) {
    u64 r; asm("fma.rn.f32x2 %0, %1, %2, %3;" : "=l"(r) : "l"(a), "l"(b), "l"(c)); return r;
}
__device__ __forceinline__ u64 shfl2(u64 v, int msk) {
    unsigned a, b;
    asm("mov.b64 {%0, %1}, %2;" : "=r"(a), "=r"(b) : "l"(v));
    a = __shfl_xor_sync(FULLMASK, a, msk);
    b = __shfl_xor_sync(FULLMASK, b, msk);
    u64 r;
    asm("mov.b64 %0, {%1, %2};" : "=l"(r) : "r"(a), "r"(b));
    return r;
}

// ---------------- Kernel A: channel-mean + patchify + projection (+ coef fold) ----------------
__global__ void proj_kernel(const float* __restrict__ x,
                            const float* __restrict__ Wp,
                            const float* __restrict__ bp,
                            const float* __restrict__ qp,
                            const float* __restrict__ kp,
                            const float* __restrict__ vp) {
    int blk = blockIdx.x;                 // 0..783 = b*196 + p
    int b = blk / NPATCH, p = blk % NPATCH;
    int py = p / 14, px = p % 14;
    int j = threadIdx.x;                  // 0..255 patch element
    int r = j >> 4, c = j & 15;
    int h = py * 16 + r, w = px * 16 + c;
    long base = (long)b * 3 * 224 * 224 + (long)h * 224 + w;
    float v = (x[base] + x[base + 224 * 224] + x[base + 2 * 224 * 224]) * (1.0f / 3.0f);

    float acc[NQ];
#pragma unroll
    for (int k = 0; k < NQ; k++) acc[k] = v * Wp[k * 256 + j];

#pragma unroll
    for (int k = 0; k < NQ; k++) {
#pragma unroll
        for (int off = 16; off; off >>= 1)
            acc[k] += __shfl_down_sync(FULLMASK, acc[k], off);
    }
    __shared__ float sred[8][NQ];
    int warp = j >> 5, lane = j & 31;
    if (lane == 0) {
#pragma unroll
        for (int k = 0; k < NQ; k++) sred[warp][k] = acc[k];
    }
    __syncthreads();
    if (j < NQ) {
        float s = 0.f;
#pragma unroll
        for (int w8 = 0; w8 < 8; w8++) s += sred[w8][j];
        g_feats[blk * NQ + j] = s + bp[j];
    }

    // folded coefficient prep (block 0 only, threads 128..247)
    if (blk == 0 && j >= 128 && j < 248) {
        int t = j - 128;
        int s = t / 40, gg = t % 40;
        const float* pp = (s == 0) ? qp : (s == 1) ? kp : vp;
        int l = gg / 20, g = gg % 20;
        float th = pp[l * 32 + g];        // pidx == gate index within layer
        float s2, c2; sincosf(2.0f * th, &s2, &c2);
        g_gcoef[s][2 * gg + 0] = 0.5f * c2;
        g_gcoef[s][2 * gg + 1] = 0.5f * s2;
    }
}

// ---------------- quantum gate primitives (packed warp-register state) ----------------
// Scalar amp index i = (lane << 7) | (k << 1) | h.
//   packed bit h      <-> qubit 11
//   A-reg bits 0..5   <-> qubits {8, 7, 4, 3, 2, 1}
//   lane bits 0..4    <-> qubits {10, 9, 6, 5, 0}
// ch = 0.5*cos2t, sh = 0.5*sin2t everywhere. neg1 = packed (-1,-1).

// w1-bit in lane (LBIT), w2-bit in A-regs (MLA); packed bit untouched
template<int LBIT, int MLA>
__device__ __forceinline__ void gM(u64* A, u64 ch2, u64 sgnsh2, u64 half2, u64 neg1) {
    const int msk = 1 << LBIT;
#pragma unroll
    for (int k = 0; k < 64; k++) {
        if ((k & MLA) == 0) {
            u64 s  = add2_(A[k], A[k | MLA]);
            u64 d  = fma2_(A[k | MLA], neg1, A[k]);
            u64 od = shfl2(d, msk);
            u64 h  = fma2_(sgnsh2, od, mul2_(ch2, d));
            u64 sv = mul2_(half2, s);
            A[k]       = add2_(sv, h);
            A[k | MLA] = fma2_(h, neg1, sv);
        }
    }
}

// w1-bit in lane (LBIT), w2-bit = packed bit
template<int LBIT>
__device__ __forceinline__ void gMp(u64* A, float ch, float sgnsh) {
    const int msk = 1 << LBIT;
#pragma unroll
    for (int k = 0; k < 64; k++) {
        float x0, x1; upk2(x0, x1, A[k]);
        float s = x0 + x1, d = x0 - x1;
        float od = __shfl_xor_sync(FULLMASK, d, msk);
        float h = fmaf(ch, d, sgnsh * od);
        float sv = 0.5f * s;
        A[k] = pk2(sv + h, sv - h);
    }
}

// w2-bit in lane (LBIT), w1-bit in A-regs (MHA); branch-free
template<int LBIT, int MHA>
__device__ __forceinline__ void gMlo(u64* A, u64 ch2, u64 sh2, u64 nsh2, u64 half2, u64 neg1) {
    const int msk = 1 << LBIT;
#pragma unroll
    for (int k = 0; k < 64; k++) {
        if ((k & MHA) == 0) {
            u64 x0 = A[k], x1 = A[k | MHA];
            u64 y0 = shfl2(x0, msk);
            u64 y1 = shfl2(x1, msk);
            u64 dx = fma2_(y0, neg1, x0);
            u64 dq = fma2_(y1, neg1, x1);
            u64 uh = mul2_(half2, add2_(x0, y0));
            u64 ph = mul2_(half2, add2_(x1, y1));
            A[k]       = fma2_(nsh2, dq, fma2_(ch2, dx, uh));
            A[k | MHA] = fma2_(ch2, dq, fma2_(sh2, dx, ph));
        }
    }
}

// both bits in A-regs (MHA = w1, MLA = w2)
template<int MHA, int MLA>
__device__ __forceinline__ void gR(u64* A, u64 ch2, u64 sh2, u64 nsh2, u64 half2, u64 neg1) {
#pragma unroll
    for (int k = 0; k < 64; k++) {
        if ((k & (MHA | MLA)) == 0) {
            u64 e00 = A[k], e01 = A[k | MLA], e10 = A[k | MHA], e11 = A[k | MHA | MLA];
            u64 u = add2_(e00, e01), v = fma2_(e01, neg1, e00);
            u64 p = add2_(e10, e11), q = fma2_(e11, neg1, e10);
            u64 hv = fma2_(nsh2, q, mul2_(ch2, v));
            u64 hq = fma2_(ch2, q, mul2_(sh2, v));
            u64 uh = mul2_(half2, u), ph = mul2_(half2, p);
            A[k]             = add2_(uh, hv);
            A[k | MLA]       = fma2_(hv, neg1, uh);
            A[k | MHA]       = add2_(ph, hq);
            A[k | MHA | MLA] = fma2_(hq, neg1, ph);
        }
    }
}

// w1-bit in A-regs (MHA), w2-bit = packed bit
template<int MHA>
__device__ __forceinline__ void gRp(u64* A, float ch, float sh) {
#pragma unroll
    for (int k = 0; k < 64; k++) {
        if ((k & MHA) == 0) {
            float e00, e01, e10, e11;
            upk2(e00, e01, A[k]);
            upk2(e10, e11, A[k | MHA]);
            float u = e00 + e01, v = e00 - e01;
            float p = e10 + e11, q = e10 - e11;
            float hv = fmaf(ch, v, -sh * q);
            float hq = fmaf(sh, v,  ch * q);
            float uh = 0.5f * u, ph = 0.5f * p;
            A[k]       = pk2(uh + hv, uh - hv);
            A[k | MHA] = pk2(ph + hq, ph - hq);
        }
    }
}

// ---------------- Kernel B: warp-per-state quantum evolution (proven R6 form) ----------------
__global__ void __launch_bounds__(128, 2) quantum_kernel() {
    int warp = threadIdx.x >> 5, lane = threadIdx.x & 31;
    int unit = blockIdx.x * 4 + warp;       // 0..2351
    int row = unit % NROWS;
    int s = unit / NROWS;                   // 0..2

    __shared__ float shco[4][80];
    {
        const float* gc = g_gcoef[s];
        for (int i = lane; i < 80; i += 32) shco[warp][i] = gc[i];
        __syncwarp();
    }
    const float* co = shco[warp];

    const u64 half2 = pk2(0.5f, 0.5f);
    const u64 neg1  = pk2(-1.0f, -1.0f);

    // angle encoding: lane q<12 computes cos/sin(x_q/2), broadcast via shfl
    float ang = (lane < NQ) ? 0.5f * g_feats[row * NQ + lane] : 0.0f;
    float cv, sv; sincosf(ang, &sv, &cv);

    // phi over lane bits: lane bit b -> qubit {10,9,6,5,0}
    float phi = 1.0f;
    {
        float cb, sb;
        cb = __shfl_sync(FULLMASK, cv, 10); sb = __shfl_sync(FULLMASK, sv, 10);
        phi *= (lane & 1)  ? sb : cb;
        cb = __shfl_sync(FULLMASK, cv, 9);  sb = __shfl_sync(FULLMASK, sv, 9);
        phi *= (lane & 2)  ? sb : cb;
        cb = __shfl_sync(FULLMASK, cv, 6);  sb = __shfl_sync(FULLMASK, sv, 6);
        phi *= (lane & 4)  ? sb : cb;
        cb = __shfl_sync(FULLMASK, cv, 5);  sb = __shfl_sync(FULLMASK, sv, 5);
        phi *= (lane & 8)  ? sb : cb;
        cb = __shfl_sync(FULLMASK, cv, 0);  sb = __shfl_sync(FULLMASK, sv, 0);
        phi *= (lane & 16) ? sb : cb;
    }

    // product-state init: packed bit -> qubit 11; A-bits 0..5 -> {8,7,4,3,2,1}
    u64 A[64];
    {
        float c11 = __shfl_sync(FULLMASK, cv, 11);
        float s11 = __shfl_sync(FULLMASK, sv, 11);
        A[0] = pk2(phi * c11, phi * s11);
        const int rq6[6] = {8, 7, 4, 3, 2, 1};
#pragma unroll
        for (int m = 0; m < 6; m++) {
            float cm = __shfl_sync(FULLMASK, cv, rq6[m]);
            float sm = __shfl_sync(FULLMASK, sv, rq6[m]);
            u64 cm2 = pk2(cm, cm), sm2 = pk2(sm, sm);
            int len = 1 << m;
#pragma unroll
            for (int i = 0; i < 64; i++) {
                if (i < len) {
                    A[i + len] = mul2_(A[i], sm2);
                    A[i] = mul2_(A[i], cm2);
                }
            }
        }
    }

    // 2 layers x 20 gates
#pragma unroll 1
    for (int l = 0; l < 2; l++) {
        const float* c = co + l * 40;
        float ch, sh; u64 ch2, sh2, nsh2;
#define LDC(g) ch = c[2*(g)]; sh = c[2*(g)+1]; ch2 = pk2(ch, ch); sh2 = pk2(sh, sh); nsh2 = pk2(-sh, -sh);
        LDC(0);  gM<4, 32>(A, ch2, (lane & 16) ? sh2 : nsh2, half2, neg1);  // (q0,q1)
        LDC(1);  gR<16, 8>(A, ch2, sh2, nsh2, half2, neg1);                 // (q2,q3)
        LDC(2);  gMlo<3, 4>(A, ch2, sh2, nsh2, half2, neg1);                // (q4,q5)
        LDC(3);  gM<2, 2>(A, ch2, (lane & 4) ? sh2 : nsh2, half2, neg1);    // (q6,q7)
        LDC(4);  gMlo<1, 1>(A, ch2, sh2, nsh2, half2, neg1);                // (q8,q9)
        LDC(5);  gMp<0>(A, ch, (lane & 1) ? sh : -sh);                      // (q10,q11)
        LDC(6);  gM<4, 16>(A, ch2, (lane & 16) ? sh2 : nsh2, half2, neg1);  // (q0,q2)
        LDC(7);  gR<32, 8>(A, ch2, sh2, nsh2, half2, neg1);                 // (q1,q3)
        LDC(8);  gMlo<2, 4>(A, ch2, sh2, nsh2, half2, neg1);                // (q4,q6)
        LDC(9);  gM<3, 2>(A, ch2, (lane & 8) ? sh2 : nsh2, half2, neg1);    // (q5,q7)
        LDC(10); gMlo<0, 1>(A, ch2, sh2, nsh2, half2, neg1);                // (q8,q10)
        LDC(11); gMp<1>(A, ch, (lane & 2) ? sh : -sh);                      // (q9,q11)
        LDC(12); gM<4, 4>(A, ch2, (lane & 16) ? sh2 : nsh2, half2, neg1);   // (q0,q4)
        LDC(13); gMlo<3, 32>(A, ch2, sh2, nsh2, half2, neg1);               // (q1,q5)
        LDC(14); gMlo<2, 16>(A, ch2, sh2, nsh2, half2, neg1);               // (q2,q6)
        LDC(15); gR<8, 2>(A, ch2, sh2, nsh2, half2, neg1);                  // (q3,q7)
        LDC(16); gM<4, 1>(A, ch2, (lane & 16) ? sh2 : nsh2, half2, neg1);   // (q0,q8)
        LDC(17); gMlo<1, 32>(A, ch2, sh2, nsh2, half2, neg1);               // (q1,q9)
        LDC(18); gMlo<0, 16>(A, ch2, sh2, nsh2, half2, neg1);               // (q2,q10)
        LDC(19); gRp<8>(A, ch, sh);                                         // (q3,q11)
#undef LDC
    }

    // expvals: squares; packed bit fold gives <Z_11>; then fold A-bits
    float D11 = 0.0f;
    float bb[64];
#pragma unroll
    for (int k = 0; k < 64; k++) {
        float x0, x1; upk2(x0, x1, A[k]);
        float s0 = x0 * x0, s1 = x1 * x1;
        D11 += s0 - s1;
        bb[k] = s0 + s1;
    }
    float D[6];
#pragma unroll
    for (int m = 0; m < 6; m++) {
        int half = 64 >> (m + 1);
        float dsum = 0.0f;
#pragma unroll
        for (int i = 0; i < 32; i++) {
            if (i < half) {
                float lo = bb[2 * i], hi = bb[2 * i + 1];
                dsum += lo - hi;
                bb[i] = lo + hi;
            }
        }
        D[m] = dsum;
    }
    float S = bb[0];                         // per-lane total prob

    // reduce D over lanes
#pragma unroll
    for (int b = 0; b < 5; b++)
        D11 += __shfl_xor_sync(FULLMASK, D11, 1 << b);
#pragma unroll
    for (int m = 0; m < 6; m++) {
#pragma unroll
        for (int b = 0; b < 5; b++)
            D[m] += __shfl_xor_sync(FULLMASK, D[m], 1 << b);
    }

    // lane-bit qubits: signed reductions of S
    float L[5];
#pragma unroll
    for (int b = 0; b < 5; b++) {
        float o = __shfl_xor_sync(FULLMASK, S, 1 << b);
        L[b] = (lane & (1 << b)) ? (o - S) : (S - o);
        S += o;
    }
#pragma unroll
    for (int b = 0; b < 5; b++) {
#pragma unroll
        for (int b2 = b + 1; b2 < 5; b2++)
            L[b] += __shfl_xor_sync(FULLMASK, L[b], 1 << b2);
    }

    if (lane == 0) {
        float* dst = g_qkv + ((long)s * NROWS + row) * NQ;
        dst[11] = D11;
        dst[8] = D[0]; dst[7] = D[1]; dst[4] = D[2];
        dst[3] = D[3]; dst[2] = D[4]; dst[1] = D[5];
        dst[10] = L[0]; dst[9] = L[1]; dst[6] = L[2]; dst[5] = L[3]; dst[0] = L[4];
    }
}

// ---------------- Kernel C: attention, warp per query row ----------------
__global__ void attn_kernel() {
    int gw = blockIdx.x * 4 + (threadIdx.x >> 5);    // 0..783
    int lane = threadIdx.x & 31;
    int b = gw / NPATCH, q = gw % NPATCH;
    const float scale = 0.28867513459481287f;        // 1/sqrt(12)

    const float* Qr = g_qkv + ((long)0 * NROWS + b * NPATCH + q) * NQ;
    const float* Kb = g_qkv + ((long)1 * NROWS + b * NPATCH) * NQ;
    const float* Vb = g_qkv + ((long)2 * NROWS + b * NPATCH) * NQ;

    float4 q0 = *(const float4*)(Qr);
    float4 q1 = *(const float4*)(Qr + 4);
    float4 q2 = *(const float4*)(Qr + 8);

    float sc[7];
    float m = -1e30f;
#pragma unroll
    for (int i = 0; i < 7; i++) {
        int k = lane + 32 * i;
        float v = -1e30f;
        if (k < NPATCH) {
            const float* Kr = Kb + k * NQ;
            float4 k0 = *(const float4*)Kr;
            float4 k1 = *(const float4*)(Kr + 4);
            float4 k2 = *(const float4*)(Kr + 8);
            v = q0.x * k0.x + q0.y * k0.y + q0.z * k0.z + q0.w * k0.w
              + q1.x * k1.x + q1.y * k1.y + q1.z * k1.z + q1.w * k1.w
              + q2.x * k2.x + q2.y * k2.y + q2.z * k2.z + q2.w * k2.w;
            v *= scale;
        }
        sc[i] = v;
        m = fmaxf(m, v);
    }
#pragma unroll
    for (int off = 16; off; off >>= 1)
        m = fmaxf(m, __shfl_xor_sync(FULLMASK, m, off));

    float den = 0.f;
    float o[NQ];
#pragma unroll
    for (int d = 0; d < NQ; d++) o[d] = 0.f;
#pragma unroll
    for (int i = 0; i < 7; i++) {
        int k = lane + 32 * i;
        if (k < NPATCH) {
            float e = __expf(sc[i] - m);
            den += e;
            const float* Vr = Vb + k * NQ;
            float4 v0 = *(const float4*)Vr;
            float4 v1 = *(const float4*)(Vr + 4);
            float4 v2 = *(const float4*)(Vr + 8);
            o[0] += e * v0.x; o[1] += e * v0.y; o[2]  += e * v0.z; o[3]  += e * v0.w;
            o[4] += e * v1.x; o[5] += e * v1.y; o[6]  += e * v1.z; o[7]  += e * v1.w;
            o[8] += e * v2.x; o[9] += e * v2.y; o[10] += e * v2.z; o[11] += e * v2.w;
        }
    }
#pragma unroll
    for (int off = 16; off; off >>= 1) {
        den += __shfl_xor_sync(FULLMASK, den, off);
#pragma unroll
        for (int d = 0; d < NQ; d++)
            o[d] += __shfl_xor_sync(FULLMASK, o[d], off);
    }
    if (lane == 0) {
        float inv = 1.0f / den;
        float* dst = g_attn_out + ((long)b * NPATCH + q) * NQ;
#pragma unroll
        for (int d = 0; d < NQ; d++) dst[d] = o[d] * inv;
    }
}

// ---------------- Kernel D: classifier (float4, proven 1000x256) ----------------
__global__ void cls_kernel(const float* __restrict__ Wc,
                           const float* __restrict__ bc,
                           float* __restrict__ out) {
    int o = blockIdx.x;                   // 0..999
    int t = threadIdx.x;                  // 256
    const float4* W4 = (const float4*)(Wc + (long)o * FEATDIM);
    const float4* A4 = (const float4*)g_attn_out;   // [4][588] float4
    float a0 = 0.f, a1 = 0.f, a2 = 0.f, a3 = 0.f;
    const int NF4 = FEATDIM / 4;          // 588
    for (int j = t; j < NF4; j += 256) {
        float4 w = W4[j];
        float4 x0 = A4[j];
        float4 x1 = A4[NF4 + j];
        float4 x2 = A4[2 * NF4 + j];
        float4 x3 = A4[3 * NF4 + j];
        a0 += w.x * x0.x + w.y * x0.y + w.z * x0.z + w.w * x0.w;
        a1 += w.x * x1.x + w.y * x1.y + w.z * x1.z + w.w * x1.w;
        a2 += w.x * x2.x + w.y * x2.y + w.z * x2.z + w.w * x2.w;
        a3 += w.x * x3.x + w.y * x3.y + w.z * x3.z + w.w * x3.w;
    }
#pragma unroll
    for (int off = 16; off; off >>= 1) {
        a0 += __shfl_down_sync(FULLMASK, a0, off);
        a1 += __shfl_down_sync(FULLMASK, a1, off);
        a2 += __shfl_down_sync(FULLMASK, a2, off);
        a3 += __shfl_down_sync(FULLMASK, a3, off);
    }
    __shared__ float sred[8][4];
    int warp = t >> 5, lane = t & 31;
    if (lane == 0) { sred[warp][0] = a0; sred[warp][1] = a1; sred[warp][2] = a2; sred[warp][3] = a3; }
    __syncthreads();
    if (t == 0) {
        float bias = bc[o];
        float r0 = 0.f, r1 = 0.f, r2 = 0.f, r3 = 0.f;
#pragma unroll
        for (int w8 = 0; w8 < 8; w8++) {
            r0 += sred[w8][0]; r1 += sred[w8][1]; r2 += sred[w8][2]; r3 += sred[w8][3];
        }
        out[0 * 1000 + o] = r0 + bias;
        out[1 * 1000 + o] = r1 + bias;
        out[2 * 1000 + o] = r2 + bias;
        out[3 * 1000 + o] = r3 + bias;
    }
}

// ---------------- launcher ----------------
extern "C" void kernel_launch(void* const* d_in, const int* in_sizes, int n_in,
                              void* d_out, int out_size) {
    const float* x  = (const float*)d_in[0];
    const float* Wp = (const float*)d_in[1];
    const float* bp = (const float*)d_in[2];
    const float* qp = (const float*)d_in[3];
    const float* kp = (const float*)d_in[4];
    const float* vp = (const float*)d_in[5];
    const float* Wc = (const float*)d_in[6];
    const float* bc = (const float*)d_in[7];
    float* out = (float*)d_out;

    proj_kernel<<<NROWS, 256>>>(x, Wp, bp, qp, kp, vp);
    quantum_kernel<<<588, 128>>>();
    attn_kernel<<<196, 128>>>();
    cls_kernel<<<1000, 256>>>(Wc, bc, out);
}